// round 3
// baseline (speedup 1.0000x reference)
#include <cuda_runtime.h>
#include <cuda_bf16.h>
#include <math.h>
#include <stdint.h>

// ---------------------------------------------------------------------------
// Problem constants: B=2, S=2048, D=1024, H=16, dh=64
// ---------------------------------------------------------------------------
#define B_  2
#define S_  2048
#define D_  1024
#define H_  16
#define DH_ 64
#define M_TOK (B_ * S_)          // 4096 tokens

// Scratch (no cudaMalloc allowed): qkv [4096,3072], attn out [4096,1024]
__device__ float g_qkv[M_TOK * 3 * D_];
__device__ float g_attn[M_TOK * D_];

// ---------------------------------------------------------------------------
// Helpers: cp.async
// ---------------------------------------------------------------------------
__device__ __forceinline__ uint32_t smem_u32(const void* p) {
    return (uint32_t)__cvta_generic_to_shared(p);
}
__device__ __forceinline__ void cp_async16(uint32_t dst, const void* src) {
    asm volatile("cp.async.cg.shared.global [%0], [%1], 16;\n" :: "r"(dst), "l"(src));
}
__device__ __forceinline__ void cp_commit() {
    asm volatile("cp.async.commit_group;\n" ::: "memory");
}
__device__ __forceinline__ void cp_wait0() {
    asm volatile("cp.async.wait_group 0;\n" ::: "memory");
}
__device__ __forceinline__ void cp_wait1() {
    asm volatile("cp.async.wait_group 1;\n" ::: "memory");
}

// ---------------------------------------------------------------------------
// SIMT fp32 SGEMM: C[M,N] = A[M,K] @ B[K,N], all row-major.
// BM=BN=128, BK=16, 256 threads, 8x8 microtile. (unchanged from R1)
// ---------------------------------------------------------------------------
#define BM 128
#define BN 128
#define BK 16
#define TM 8
#define TN 8

__global__ __launch_bounds__(256) void sgemm_kernel(
    const float* __restrict__ A, const float* __restrict__ Bm,
    float* __restrict__ C, int M, int N, int K)
{
    __shared__ float As[BK][BM];
    __shared__ float Bs[BK][BN];

    const int tid = threadIdx.x;
    const int bm = blockIdx.y * BM;
    const int bn = blockIdx.x * BN;

    const int tr = (tid / (BN / TN)) * TM;
    const int tc = (tid % (BN / TN)) * TN;

    float acc[TM][TN];
#pragma unroll
    for (int i = 0; i < TM; i++)
#pragma unroll
        for (int j = 0; j < TN; j++) acc[i][j] = 0.f;

    for (int k0 = 0; k0 < K; k0 += BK) {
#pragma unroll
        for (int it = 0; it < (BM * BK) / (256 * 4); ++it) {
            int idx = tid + it * 256;
            int r   = idx / (BK / 4);
            int c4  = idx % (BK / 4);
            float4 v = *(const float4*)&A[(size_t)(bm + r) * K + k0 + c4 * 4];
            As[c4 * 4 + 0][r] = v.x;
            As[c4 * 4 + 1][r] = v.y;
            As[c4 * 4 + 2][r] = v.z;
            As[c4 * 4 + 3][r] = v.w;
        }
#pragma unroll
        for (int it = 0; it < (BK * BN) / (256 * 4); ++it) {
            int idx = tid + it * 256;
            int r   = idx / (BN / 4);
            int c4  = idx % (BN / 4);
            *(float4*)&Bs[r][c4 * 4] =
                *(const float4*)&Bm[(size_t)(k0 + r) * N + bn + c4 * 4];
        }
        __syncthreads();

#pragma unroll
        for (int k = 0; k < BK; ++k) {
            float a[TM], b[TN];
#pragma unroll
            for (int i = 0; i < TM; i++) a[i] = As[k][tr + i];
#pragma unroll
            for (int j = 0; j < TN; j++) b[j] = Bs[k][tc + j];
#pragma unroll
            for (int i = 0; i < TM; i++)
#pragma unroll
                for (int j = 0; j < TN; j++) acc[i][j] += a[i] * b[j];
        }
        __syncthreads();
    }

#pragma unroll
    for (int i = 0; i < TM; i++)
#pragma unroll
        for (int j = 0; j < TN; j += 4) {
            float4 v = make_float4(acc[i][j], acc[i][j + 1], acc[i][j + 2], acc[i][j + 3]);
            *(float4*)&C[(size_t)(bm + tr + i) * N + bn + tc + j] = v;
        }
}

// ---------------------------------------------------------------------------
// Flash attention v2 (fp32, register-blocked 4x4, cp.async double buffering).
// One block = (b, h, 64-query tile). 256 threads.
// Thread (rg = tid>>4, cg = tid&15): owns a 4x4 microtile:
//   QK phase: rows tr..tr+3 (tr = rg*4), cols {cg + 16*j}, j=0..3
//   PV phase: rows tr..tr+3, dh-cols cg*4..cg*4+3
// Smem: Qs[64][68], Ks[2][64][68], Vs[2][64][68], Pt[64][68] (Pt row = key)
// ---------------------------------------------------------------------------
#define SD 68
#define ATTN_SMEM (6 * 64 * SD * sizeof(float))   // 104448 bytes
#define NEG_INF_F (-1e30f)

__global__ __launch_bounds__(256, 2) void attn_kernel(
    const float* __restrict__ qkv, float* __restrict__ out)
{
    const int qt  = (int)gridDim.x - 1 - (int)blockIdx.x;  // heavy blocks first
    const int h   = blockIdx.y;
    const int b   = blockIdx.z;
    const int tid = threadIdx.x;
    const int rg  = tid >> 4;
    const int cg  = tid & 15;
    const int tr  = rg * 4;

    extern __shared__ float sm[];
    float* Qs = sm;                    // [64][SD]
    float* Ks = sm + 64 * SD;          // [2][64][SD]
    float* Vs = sm + 3 * 64 * SD;      // [2][64][SD]
    float* Pt = sm + 5 * 64 * SD;      // [64][SD]   (row = key idx, col = query idx)

    const float scale = 0.125f;        // dh^-0.5
    const size_t base = (size_t)b * S_ * 3 * D_ + (size_t)h * DH_;

    // --- load Q tile (plain LDG->STS; overlapped with first cp.async) ---
    // Issue K/V tile 0 first so DRAM latency overlaps the Q loads.
    {
        // cp.async K/V for kt = 0 into buffer 0
        for (int i = tid; i < 64 * 16; i += 256) {
            int r = i >> 4, c4 = i & 15;
            size_t g = base + (size_t)(r) * 3 * D_ + c4 * 4;   // kt = 0
            cp_async16(smem_u32(&Ks[(size_t)r * SD + c4 * 4]), &qkv[g + D_]);
            cp_async16(smem_u32(&Vs[(size_t)r * SD + c4 * 4]), &qkv[g + 2 * D_]);
        }
        cp_commit();
        for (int i = tid; i < 64 * 16; i += 256) {
            int r = i >> 4, c4 = i & 15;
            *(float4*)&Qs[(size_t)r * SD + c4 * 4] =
                *(const float4*)&qkv[base + (size_t)(qt * 64 + r) * 3 * D_ + c4 * 4];
        }
    }

    float m[4], l[4], o[4][4];
#pragma unroll
    for (int i = 0; i < 4; i++) {
        m[i] = NEG_INF_F; l[i] = 0.f;
#pragma unroll
        for (int j = 0; j < 4; j++) o[i][j] = 0.f;
    }

    const int n_tiles = qt + 1;
    for (int kt = 0; kt < n_tiles; ++kt) {
        const int buf = kt & 1;
        if (kt > 0) __syncthreads();   // everyone done with buf^1 from iter kt-1

        if (kt + 1 < n_tiles) {
            float* Kn = &Ks[(size_t)(buf ^ 1) * 64 * SD];
            float* Vn = &Vs[(size_t)(buf ^ 1) * 64 * SD];
            for (int i = tid; i < 64 * 16; i += 256) {
                int r = i >> 4, c4 = i & 15;
                size_t g = base + (size_t)((kt + 1) * 64 + r) * 3 * D_ + c4 * 4;
                cp_async16(smem_u32(&Kn[(size_t)r * SD + c4 * 4]), &qkv[g + D_]);
                cp_async16(smem_u32(&Vn[(size_t)r * SD + c4 * 4]), &qkv[g + 2 * D_]);
            }
            cp_commit();
            cp_wait1();                // tile kt finished
        } else {
            cp_wait0();
        }
        __syncthreads();               // tile kt visible to all

        const float* Kb = &Ks[(size_t)buf * 64 * SD];
        const float* Vb = &Vs[(size_t)buf * 64 * SD];

        // ---- scores: s[i][j] = Q[tr+i,:] . K[cg+16j,:] ----
        float s[4][4];
#pragma unroll
        for (int i = 0; i < 4; i++)
#pragma unroll
            for (int j = 0; j < 4; j++) s[i][j] = 0.f;

#pragma unroll
        for (int k = 0; k < DH_; k += 4) {
            float4 q4[4];
#pragma unroll
            for (int i = 0; i < 4; i++) q4[i] = *(float4*)&Qs[(size_t)(tr + i) * SD + k];
#pragma unroll
            for (int j = 0; j < 4; j++) {
                float4 k4 = *(const float4*)&Kb[(size_t)(cg + 16 * j) * SD + k];
#pragma unroll
                for (int i = 0; i < 4; i++) {
                    s[i][j] += q4[i].x * k4.x + q4[i].y * k4.y
                             + q4[i].z * k4.z + q4[i].w * k4.w;
                }
            }
        }

        // ---- causal mask + scale + online softmax ----
        const bool interior = (kt < qt);
        float corr[4];
#pragma unroll
        for (int i = 0; i < 4; i++) {
            const int gq = qt * 64 + tr + i;
            float mloc = NEG_INF_F;
#pragma unroll
            for (int j = 0; j < 4; j++) {
                int gk = kt * 64 + cg + 16 * j;
                bool ok = interior || (gk <= gq);
                s[i][j] = ok ? s[i][j] * scale : NEG_INF_F;
                mloc = fmaxf(mloc, s[i][j]);
            }
            mloc = fmaxf(mloc, __shfl_xor_sync(0xffffffffu, mloc, 1));
            mloc = fmaxf(mloc, __shfl_xor_sync(0xffffffffu, mloc, 2));
            mloc = fmaxf(mloc, __shfl_xor_sync(0xffffffffu, mloc, 4));
            mloc = fmaxf(mloc, __shfl_xor_sync(0xffffffffu, mloc, 8));
            const float mnew = fmaxf(m[i], mloc);
            corr[i] = __expf(m[i] - mnew);
            m[i] = mnew;
        }
#pragma unroll
        for (int i = 0; i < 4; i++) {
            float psum = 0.f;
#pragma unroll
            for (int j = 0; j < 4; j++) {
                s[i][j] = __expf(s[i][j] - m[i]);
                psum += s[i][j];
            }
            psum += __shfl_xor_sync(0xffffffffu, psum, 1);
            psum += __shfl_xor_sync(0xffffffffu, psum, 2);
            psum += __shfl_xor_sync(0xffffffffu, psum, 4);
            psum += __shfl_xor_sync(0xffffffffu, psum, 8);
            l[i] = l[i] * corr[i] + psum;
#pragma unroll
            for (int j = 0; j < 4; j++) o[i][j] *= corr[i];
        }

        // ---- stage P transposed: Pt[key][query] ----
#pragma unroll
        for (int j = 0; j < 4; j++) {
            float4 v = make_float4(s[0][j], s[1][j], s[2][j], s[3][j]);
            *(float4*)&Pt[(size_t)(cg + 16 * j) * SD + tr] = v;
        }
        __syncthreads();

        // ---- PV: o[i][j] += sum_c Pt[c][tr+i] * V[c][cg*4+j] ----
#pragma unroll 4
        for (int c = 0; c < 64; ++c) {
            float4 p4 = *(float4*)&Pt[(size_t)c * SD + tr];
            float4 v4 = *(const float4*)&Vb[(size_t)c * SD + cg * 4];
            o[0][0] += p4.x * v4.x; o[0][1] += p4.x * v4.y;
            o[0][2] += p4.x * v4.z; o[0][3] += p4.x * v4.w;
            o[1][0] += p4.y * v4.x; o[1][1] += p4.y * v4.y;
            o[1][2] += p4.y * v4.z; o[1][3] += p4.y * v4.w;
            o[2][0] += p4.z * v4.x; o[2][1] += p4.z * v4.y;
            o[2][2] += p4.z * v4.z; o[2][3] += p4.z * v4.w;
            o[3][0] += p4.w * v4.x; o[3][1] += p4.w * v4.y;
            o[3][2] += p4.w * v4.z; o[3][3] += p4.w * v4.w;
        }
    }

    // ---- epilogue: normalize + store to [b, s, h*dh + d] ----
#pragma unroll
    for (int i = 0; i < 4; i++) {
        const float inv = 1.f / l[i];
        float4 v = make_float4(o[i][0] * inv, o[i][1] * inv,
                               o[i][2] * inv, o[i][3] * inv);
        const size_t ob = ((size_t)(b * S_ + qt * 64 + tr + i)) * D_ + h * DH_ + cg * 4;
        *(float4*)&out[ob] = v;
    }
}

// ---------------------------------------------------------------------------
// Launch
// ---------------------------------------------------------------------------
extern "C" void kernel_launch(void* const* d_in, const int* in_sizes, int n_in,
                              void* d_out, int out_size)
{
    const float* x     = (const float*)d_in[0];   // [4096,1024]
    const float* w_qkv = (const float*)d_in[1];   // [1024,3072]
    const float* w_out = (const float*)d_in[2];   // [1024,1024]
    float* out = (float*)d_out;                   // [4096,1024]

    float* qkv = nullptr;
    float* attn = nullptr;
    cudaGetSymbolAddress((void**)&qkv, g_qkv);
    cudaGetSymbolAddress((void**)&attn, g_attn);

    // 1) QKV projection: [4096,1024] @ [1024,3072]
    {
        dim3 grid(3 * D_ / BN, M_TOK / BM);
        sgemm_kernel<<<grid, 256>>>(x, w_qkv, qkv, M_TOK, 3 * D_, D_);
    }

    // 2) Flash attention (v2)
    {
        cudaFuncSetAttribute(attn_kernel,
                             cudaFuncAttributeMaxDynamicSharedMemorySize,
                             (int)ATTN_SMEM);
        dim3 grid(S_ / 64, H_, B_);
        attn_kernel<<<grid, 256, ATTN_SMEM>>>(qkv, attn);
    }

    // 3) Output projection: [4096,1024] @ [1024,1024]
    {
        dim3 grid(D_ / BN, M_TOK / BM);
        sgemm_kernel<<<grid, 256>>>(attn, w_out, out, M_TOK, D_, D_);
    }
}

// round 4
// speedup vs baseline: 1.7222x; 1.7222x over previous
#include <cuda_runtime.h>
#include <cuda_bf16.h>
#include <math.h>
#include <stdint.h>

// ---------------------------------------------------------------------------
// Problem constants: B=2, S=2048, D=1024, H=16, dh=64
// ---------------------------------------------------------------------------
#define B_  2
#define S_  2048
#define D_  1024
#define H_  16
#define DH_ 64
#define M_TOK (B_ * S_)          // 4096 tokens

// Scratch (no cudaMalloc allowed)
__device__ float g_qkv[M_TOK * 3 * D_];    // qkv activations
__device__ float g_attn[M_TOK * D_];       // attention output (tf32-rounded)
__device__ float g_x[M_TOK * D_];          // tf32-rounded x
__device__ float g_wqkv[D_ * 3 * D_];      // tf32-rounded w_qkv
__device__ float g_wout[D_ * D_];          // tf32-rounded w_out

// ---------------------------------------------------------------------------
// Helpers
// ---------------------------------------------------------------------------
__device__ __forceinline__ uint32_t smem_u32(const void* p) {
    return (uint32_t)__cvta_generic_to_shared(p);
}
__device__ __forceinline__ void cp_async16(uint32_t dst, const void* src) {
    asm volatile("cp.async.cg.shared.global [%0], [%1], 16;\n" :: "r"(dst), "l"(src));
}
__device__ __forceinline__ void cp_commit() {
    asm volatile("cp.async.commit_group;\n" ::: "memory");
}
__device__ __forceinline__ void cp_wait0() {
    asm volatile("cp.async.wait_group 0;\n" ::: "memory");
}
__device__ __forceinline__ void cp_wait1() {
    asm volatile("cp.async.wait_group 1;\n" ::: "memory");
}
__device__ __forceinline__ float round_tf32(float v) {
    uint32_t r;
    asm("cvt.rna.tf32.f32 %0, %1;" : "=r"(r) : "f"(v));
    return __uint_as_float(r);
}
__device__ __forceinline__ void mma_tf32_16x8x8(
    float& c0, float& c1, float& c2, float& c3,
    uint32_t a0, uint32_t a1, uint32_t a2, uint32_t a3,
    uint32_t b0, uint32_t b1)
{
    asm volatile(
        "mma.sync.aligned.m16n8k8.row.col.f32.tf32.tf32.f32 "
        "{%0,%1,%2,%3}, {%4,%5,%6,%7}, {%8,%9}, {%0,%1,%2,%3};\n"
        : "+f"(c0), "+f"(c1), "+f"(c2), "+f"(c3)
        : "r"(a0), "r"(a1), "r"(a2), "r"(a3), "r"(b0), "r"(b1));
}

// ---------------------------------------------------------------------------
// Elementwise tf32 pre-rounding (grid-stride float4)
// ---------------------------------------------------------------------------
__global__ void round_tf32_kernel(const float* __restrict__ in,
                                  float* __restrict__ out, int n4)
{
    for (int i = blockIdx.x * blockDim.x + threadIdx.x; i < n4;
         i += gridDim.x * blockDim.x) {
        float4 v = ((const float4*)in)[i];
        v.x = round_tf32(v.x); v.y = round_tf32(v.y);
        v.z = round_tf32(v.z); v.w = round_tf32(v.w);
        ((float4*)out)[i] = v;
    }
}

// ---------------------------------------------------------------------------
// TF32 tensor-core GEMM: C[M,N] = A[M,K] @ B[K,N], row-major, tf32-exact inputs.
// Block 128x128, BK=32, 256 threads = 8 warps (4m x 2n), warp tile 32x64.
// Smem: As[2][128][36] (row-major, pad->conflict-free frag loads),
//       Bs[2][32][136]  (row-major k x n, pad 8 -> conflict-free)
// ---------------------------------------------------------------------------
#define GBM 128
#define GBN 128
#define GBK 32
#define A_STRIDE 36
#define B_STRIDE 136
#define A_BUF (GBM * A_STRIDE)            // floats per A buffer
#define B_BUF (GBK * B_STRIDE)            // floats per B buffer
#define GEMM_SMEM ((2 * A_BUF + 2 * B_BUF) * sizeof(float))  // 71680 B

__global__ __launch_bounds__(256, 2) void mma_gemm_kernel(
    const float* __restrict__ A, const float* __restrict__ Bm,
    float* __restrict__ C, int M, int N, int K)
{
    extern __shared__ float sm[];
    float* As = sm;                 // [2][128][36]
    float* Bs = sm + 2 * A_BUF;     // [2][32][136]

    const int tid  = threadIdx.x;
    const int warp = tid >> 5;
    const int lane = tid & 31;
    const int g    = lane >> 2;     // 0..7
    const int tg   = lane & 3;      // 0..3

    const int bm = blockIdx.y * GBM;
    const int bn = blockIdx.x * GBN;
    const int wm = (warp & 3) * 32; // warp row offset in tile
    const int wn = (warp >> 2) * 64;

    float c[2][8][4];
#pragma unroll
    for (int mt = 0; mt < 2; mt++)
#pragma unroll
        for (int nt = 0; nt < 8; nt++)
#pragma unroll
            for (int i = 0; i < 4; i++) c[mt][nt][i] = 0.f;

    // ---- async load of one (A,B) tile pair into buffer `buf` ----
    auto load_tiles = [&](int k0, int buf) {
        float* Ab = As + buf * A_BUF;
        float* Bb = Bs + buf * B_BUF;
        // A: 128x32 floats = 1024 float4; 4 per thread
#pragma unroll
        for (int it = 0; it < 4; ++it) {
            int idx = tid + it * 256;
            int r = idx >> 3, c4 = idx & 7;
            cp_async16(smem_u32(&Ab[r * A_STRIDE + c4 * 4]),
                       &A[(size_t)(bm + r) * K + k0 + c4 * 4]);
        }
        // B: 32x128 floats = 1024 float4; 4 per thread
#pragma unroll
        for (int it = 0; it < 4; ++it) {
            int idx = tid + it * 256;
            int r = idx >> 5, c4 = idx & 31;
            cp_async16(smem_u32(&Bb[r * B_STRIDE + c4 * 4]),
                       &Bm[(size_t)(k0 + r) * N + bn + c4 * 4]);
        }
        cp_commit();
    };

    load_tiles(0, 0);

    const int n_k = K / GBK;
    for (int kt = 0; kt < n_k; ++kt) {
        const int buf = kt & 1;
        if (kt + 1 < n_k) {
            load_tiles((kt + 1) * GBK, buf ^ 1);
            cp_wait1();
        } else {
            cp_wait0();
        }
        __syncthreads();

        const float* Ab = As + buf * A_BUF;
        const float* Bb = Bs + buf * B_BUF;

#pragma unroll
        for (int kk = 0; kk < GBK; kk += 8) {
            uint32_t a[2][4];
#pragma unroll
            for (int mt = 0; mt < 2; mt++) {
                const int r0 = wm + mt * 16 + g;
                a[mt][0] = __float_as_uint(Ab[(r0)     * A_STRIDE + kk + tg]);
                a[mt][1] = __float_as_uint(Ab[(r0 + 8) * A_STRIDE + kk + tg]);
                a[mt][2] = __float_as_uint(Ab[(r0)     * A_STRIDE + kk + tg + 4]);
                a[mt][3] = __float_as_uint(Ab[(r0 + 8) * A_STRIDE + kk + tg + 4]);
            }
#pragma unroll
            for (int nt = 0; nt < 8; nt++) {
                const int col = wn + nt * 8 + g;
                uint32_t b0 = __float_as_uint(Bb[(kk + tg)     * B_STRIDE + col]);
                uint32_t b1 = __float_as_uint(Bb[(kk + tg + 4) * B_STRIDE + col]);
#pragma unroll
                for (int mt = 0; mt < 2; mt++) {
                    mma_tf32_16x8x8(c[mt][nt][0], c[mt][nt][1],
                                    c[mt][nt][2], c[mt][nt][3],
                                    a[mt][0], a[mt][1], a[mt][2], a[mt][3],
                                    b0, b1);
                }
            }
        }
        __syncthreads();
    }

    // ---- epilogue ----
#pragma unroll
    for (int mt = 0; mt < 2; mt++) {
        const int r0 = bm + wm + mt * 16 + g;
#pragma unroll
        for (int nt = 0; nt < 8; nt++) {
            const int col = bn + wn + nt * 8 + tg * 2;
            *(float2*)&C[(size_t)r0 * N + col]       = make_float2(c[mt][nt][0], c[mt][nt][1]);
            *(float2*)&C[(size_t)(r0 + 8) * N + col] = make_float2(c[mt][nt][2], c[mt][nt][3]);
        }
    }
}

// ---------------------------------------------------------------------------
// Flash attention v2 (fp32, register-blocked 4x4, cp.async double buffering).
// (unchanged from R2 except tf32-rounded epilogue writes)
// ---------------------------------------------------------------------------
#define SD 68
#define ATTN_SMEM (6 * 64 * SD * sizeof(float))   // 104448 bytes
#define NEG_INF_F (-1e30f)

__global__ __launch_bounds__(256, 2) void attn_kernel(
    const float* __restrict__ qkv, float* __restrict__ out)
{
    const int qt  = (int)gridDim.x - 1 - (int)blockIdx.x;  // heavy blocks first
    const int h   = blockIdx.y;
    const int b   = blockIdx.z;
    const int tid = threadIdx.x;
    const int rg  = tid >> 4;
    const int cg  = tid & 15;
    const int tr  = rg * 4;

    extern __shared__ float sm[];
    float* Qs = sm;                    // [64][SD]
    float* Ks = sm + 64 * SD;          // [2][64][SD]
    float* Vs = sm + 3 * 64 * SD;      // [2][64][SD]
    float* Pt = sm + 5 * 64 * SD;      // [64][SD]

    const float scale = 0.125f;
    const size_t base = (size_t)b * S_ * 3 * D_ + (size_t)h * DH_;

    {
        for (int i = tid; i < 64 * 16; i += 256) {
            int r = i >> 4, c4 = i & 15;
            size_t g = base + (size_t)(r) * 3 * D_ + c4 * 4;   // kt = 0
            cp_async16(smem_u32(&Ks[(size_t)r * SD + c4 * 4]), &qkv[g + D_]);
            cp_async16(smem_u32(&Vs[(size_t)r * SD + c4 * 4]), &qkv[g + 2 * D_]);
        }
        cp_commit();
        for (int i = tid; i < 64 * 16; i += 256) {
            int r = i >> 4, c4 = i & 15;
            *(float4*)&Qs[(size_t)r * SD + c4 * 4] =
                *(const float4*)&qkv[base + (size_t)(qt * 64 + r) * 3 * D_ + c4 * 4];
        }
    }

    float m[4], l[4], o[4][4];
#pragma unroll
    for (int i = 0; i < 4; i++) {
        m[i] = NEG_INF_F; l[i] = 0.f;
#pragma unroll
        for (int j = 0; j < 4; j++) o[i][j] = 0.f;
    }

    const int n_tiles = qt + 1;
    for (int kt = 0; kt < n_tiles; ++kt) {
        const int buf = kt & 1;
        if (kt > 0) __syncthreads();

        if (kt + 1 < n_tiles) {
            float* Kn = &Ks[(size_t)(buf ^ 1) * 64 * SD];
            float* Vn = &Vs[(size_t)(buf ^ 1) * 64 * SD];
            for (int i = tid; i < 64 * 16; i += 256) {
                int r = i >> 4, c4 = i & 15;
                size_t g = base + (size_t)((kt + 1) * 64 + r) * 3 * D_ + c4 * 4;
                cp_async16(smem_u32(&Kn[(size_t)r * SD + c4 * 4]), &qkv[g + D_]);
                cp_async16(smem_u32(&Vn[(size_t)r * SD + c4 * 4]), &qkv[g + 2 * D_]);
            }
            cp_commit();
            cp_wait1();
        } else {
            cp_wait0();
        }
        __syncthreads();

        const float* Kb = &Ks[(size_t)buf * 64 * SD];
        const float* Vb = &Vs[(size_t)buf * 64 * SD];

        float s[4][4];
#pragma unroll
        for (int i = 0; i < 4; i++)
#pragma unroll
            for (int j = 0; j < 4; j++) s[i][j] = 0.f;

#pragma unroll
        for (int k = 0; k < DH_; k += 4) {
            float4 q4[4];
#pragma unroll
            for (int i = 0; i < 4; i++) q4[i] = *(float4*)&Qs[(size_t)(tr + i) * SD + k];
#pragma unroll
            for (int j = 0; j < 4; j++) {
                float4 k4 = *(const float4*)&Kb[(size_t)(cg + 16 * j) * SD + k];
#pragma unroll
                for (int i = 0; i < 4; i++) {
                    s[i][j] += q4[i].x * k4.x + q4[i].y * k4.y
                             + q4[i].z * k4.z + q4[i].w * k4.w;
                }
            }
        }

        const bool interior = (kt < qt);
        float corr[4];
#pragma unroll
        for (int i = 0; i < 4; i++) {
            const int gq = qt * 64 + tr + i;
            float mloc = NEG_INF_F;
#pragma unroll
            for (int j = 0; j < 4; j++) {
                int gk = kt * 64 + cg + 16 * j;
                bool ok = interior || (gk <= gq);
                s[i][j] = ok ? s[i][j] * scale : NEG_INF_F;
                mloc = fmaxf(mloc, s[i][j]);
            }
            mloc = fmaxf(mloc, __shfl_xor_sync(0xffffffffu, mloc, 1));
            mloc = fmaxf(mloc, __shfl_xor_sync(0xffffffffu, mloc, 2));
            mloc = fmaxf(mloc, __shfl_xor_sync(0xffffffffu, mloc, 4));
            mloc = fmaxf(mloc, __shfl_xor_sync(0xffffffffu, mloc, 8));
            const float mnew = fmaxf(m[i], mloc);
            corr[i] = __expf(m[i] - mnew);
            m[i] = mnew;
        }
#pragma unroll
        for (int i = 0; i < 4; i++) {
            float psum = 0.f;
#pragma unroll
            for (int j = 0; j < 4; j++) {
                s[i][j] = __expf(s[i][j] - m[i]);
                psum += s[i][j];
            }
            psum += __shfl_xor_sync(0xffffffffu, psum, 1);
            psum += __shfl_xor_sync(0xffffffffu, psum, 2);
            psum += __shfl_xor_sync(0xffffffffu, psum, 4);
            psum += __shfl_xor_sync(0xffffffffu, psum, 8);
            l[i] = l[i] * corr[i] + psum;
#pragma unroll
            for (int j = 0; j < 4; j++) o[i][j] *= corr[i];
        }

#pragma unroll
        for (int j = 0; j < 4; j++) {
            float4 v = make_float4(s[0][j], s[1][j], s[2][j], s[3][j]);
            *(float4*)&Pt[(size_t)(cg + 16 * j) * SD + tr] = v;
        }
        __syncthreads();

#pragma unroll 4
        for (int c = 0; c < 64; ++c) {
            float4 p4 = *(float4*)&Pt[(size_t)c * SD + tr];
            float4 v4 = *(const float4*)&Vb[(size_t)c * SD + cg * 4];
            o[0][0] += p4.x * v4.x; o[0][1] += p4.x * v4.y;
            o[0][2] += p4.x * v4.z; o[0][3] += p4.x * v4.w;
            o[1][0] += p4.y * v4.x; o[1][1] += p4.y * v4.y;
            o[1][2] += p4.y * v4.z; o[1][3] += p4.y * v4.w;
            o[2][0] += p4.z * v4.x; o[2][1] += p4.z * v4.y;
            o[2][2] += p4.z * v4.z; o[2][3] += p4.z * v4.w;
            o[3][0] += p4.w * v4.x; o[3][1] += p4.w * v4.y;
            o[3][2] += p4.w * v4.z; o[3][3] += p4.w * v4.w;
        }
    }

    // epilogue: normalize + tf32-round (feeds tensor-core out-proj) + store
#pragma unroll
    for (int i = 0; i < 4; i++) {
        const float inv = 1.f / l[i];
        float4 v = make_float4(round_tf32(o[i][0] * inv), round_tf32(o[i][1] * inv),
                               round_tf32(o[i][2] * inv), round_tf32(o[i][3] * inv));
        const size_t ob = ((size_t)(b * S_ + qt * 64 + tr + i)) * D_ + h * DH_ + cg * 4;
        *(float4*)&out[ob] = v;
    }
}

// ---------------------------------------------------------------------------
// Launch
// ---------------------------------------------------------------------------
extern "C" void kernel_launch(void* const* d_in, const int* in_sizes, int n_in,
                              void* d_out, int out_size)
{
    const float* x     = (const float*)d_in[0];   // [4096,1024]
    const float* w_qkv = (const float*)d_in[1];   // [1024,3072]
    const float* w_out = (const float*)d_in[2];   // [1024,1024]
    float* out = (float*)d_out;                   // [4096,1024]

    float *qkv, *attn, *xr, *wqkvr, *woutr;
    cudaGetSymbolAddress((void**)&qkv,   g_qkv);
    cudaGetSymbolAddress((void**)&attn,  g_attn);
    cudaGetSymbolAddress((void**)&xr,    g_x);
    cudaGetSymbolAddress((void**)&wqkvr, g_wqkv);
    cudaGetSymbolAddress((void**)&woutr, g_wout);

    // 0) Pre-round all GEMM operands to exact tf32 values (round-to-nearest)
    round_tf32_kernel<<<592, 256>>>(x,     xr,    M_TOK * D_ / 4);
    round_tf32_kernel<<<592, 256>>>(w_qkv, wqkvr, D_ * 3 * D_ / 4);
    round_tf32_kernel<<<592, 256>>>(w_out, woutr, D_ * D_ / 4);

    // 1) QKV projection (tf32 tensor cores): [4096,1024] @ [1024,3072]
    {
        cudaFuncSetAttribute(mma_gemm_kernel,
                             cudaFuncAttributeMaxDynamicSharedMemorySize,
                             (int)GEMM_SMEM);
        dim3 grid(3 * D_ / GBN, M_TOK / GBM);
        mma_gemm_kernel<<<grid, 256, GEMM_SMEM>>>(xr, wqkvr, qkv, M_TOK, 3 * D_, D_);
    }

    // 2) Flash attention (fp32; epilogue rounds to tf32 for the next GEMM)
    {
        cudaFuncSetAttribute(attn_kernel,
                             cudaFuncAttributeMaxDynamicSharedMemorySize,
                             (int)ATTN_SMEM);
        dim3 grid(S_ / 64, H_, B_);
        attn_kernel<<<grid, 256, ATTN_SMEM>>>(qkv, attn);
    }

    // 3) Output projection (tf32 tensor cores): [4096,1024] @ [1024,1024]
    {
        dim3 grid(D_ / GBN, M_TOK / GBM);
        mma_gemm_kernel<<<grid, 256, GEMM_SMEM>>>(attn, woutr, out, M_TOK, D_, D_);
    }
}

// round 5
// speedup vs baseline: 3.1476x; 1.8277x over previous
#include <cuda_runtime.h>
#include <cuda_bf16.h>
#include <math.h>
#include <stdint.h>

// ---------------------------------------------------------------------------
// Problem constants: B=2, S=2048, D=1024, H=16, dh=64
// ---------------------------------------------------------------------------
#define B_  2
#define S_  2048
#define D_  1024
#define H_  16
#define DH_ 64
#define M_TOK (B_ * S_)          // 4096 tokens

// Scratch (no cudaMalloc allowed)
__device__ float g_qkv[M_TOK * 3 * D_];    // qkv activations (tf32-exact)
__device__ float g_attn[M_TOK * D_];       // attention output (tf32-exact)
__device__ float g_x[M_TOK * D_];          // tf32-rounded x
__device__ float g_wqkv[D_ * 3 * D_];      // tf32-rounded w_qkv
__device__ float g_wout[D_ * D_];          // tf32-rounded w_out

// ---------------------------------------------------------------------------
// Helpers
// ---------------------------------------------------------------------------
__device__ __forceinline__ uint32_t smem_u32(const void* p) {
    return (uint32_t)__cvta_generic_to_shared(p);
}
__device__ __forceinline__ void cp_async16(uint32_t dst, const void* src) {
    asm volatile("cp.async.cg.shared.global [%0], [%1], 16;\n" :: "r"(dst), "l"(src));
}
__device__ __forceinline__ void cp_commit() {
    asm volatile("cp.async.commit_group;\n" ::: "memory");
}
__device__ __forceinline__ void cp_wait0() {
    asm volatile("cp.async.wait_group 0;\n" ::: "memory");
}
__device__ __forceinline__ void cp_wait1() {
    asm volatile("cp.async.wait_group 1;\n" ::: "memory");
}
__device__ __forceinline__ float round_tf32(float v) {
    uint32_t r;
    asm("cvt.rna.tf32.f32 %0, %1;" : "=r"(r) : "f"(v));
    return __uint_as_float(r);
}
__device__ __forceinline__ void mma_tf32_16x8x8(
    float* c,
    uint32_t a0, uint32_t a1, uint32_t a2, uint32_t a3,
    uint32_t b0, uint32_t b1)
{
    asm volatile(
        "mma.sync.aligned.m16n8k8.row.col.f32.tf32.tf32.f32 "
        "{%0,%1,%2,%3}, {%4,%5,%6,%7}, {%8,%9}, {%0,%1,%2,%3};\n"
        : "+f"(c[0]), "+f"(c[1]), "+f"(c[2]), "+f"(c[3])
        : "r"(a0), "r"(a1), "r"(a2), "r"(a3), "r"(b0), "r"(b1));
}

// ---------------------------------------------------------------------------
// Elementwise tf32 pre-rounding (grid-stride float4)
// ---------------------------------------------------------------------------
__global__ void round_tf32_kernel(const float* __restrict__ in,
                                  float* __restrict__ out, int n4)
{
    for (int i = blockIdx.x * blockDim.x + threadIdx.x; i < n4;
         i += gridDim.x * blockDim.x) {
        float4 v = ((const float4*)in)[i];
        v.x = round_tf32(v.x); v.y = round_tf32(v.y);
        v.z = round_tf32(v.z); v.w = round_tf32(v.w);
        ((float4*)out)[i] = v;
    }
}

// ---------------------------------------------------------------------------
// TF32 tensor-core GEMM: C[M,N] = A[M,K] @ B[K,N], row-major, tf32-exact inputs.
// Block 128x128, BK=32, 256 threads = 8 warps (4m x 2n), warp tile 32x64.
// round_out != 0 -> epilogue writes tf32-rounded values (feeds next tf32 GEMM)
// ---------------------------------------------------------------------------
#define GBM 128
#define GBN 128
#define GBK 32
#define A_STRIDE 36
#define B_STRIDE 136
#define A_BUF (GBM * A_STRIDE)
#define B_BUF (GBK * B_STRIDE)
#define GEMM_SMEM ((2 * A_BUF + 2 * B_BUF) * sizeof(float))  // 71680 B

__global__ __launch_bounds__(256, 2) void mma_gemm_kernel(
    const float* __restrict__ A, const float* __restrict__ Bm,
    float* __restrict__ C, int M, int N, int K, int round_out)
{
    extern __shared__ float sm[];
    float* As = sm;
    float* Bs = sm + 2 * A_BUF;

    const int tid  = threadIdx.x;
    const int warp = tid >> 5;
    const int lane = tid & 31;
    const int g    = lane >> 2;
    const int tg   = lane & 3;

    const int bm = blockIdx.y * GBM;
    const int bn = blockIdx.x * GBN;
    const int wm = (warp & 3) * 32;
    const int wn = (warp >> 2) * 64;

    float c[2][8][4];
#pragma unroll
    for (int mt = 0; mt < 2; mt++)
#pragma unroll
        for (int nt = 0; nt < 8; nt++)
#pragma unroll
            for (int i = 0; i < 4; i++) c[mt][nt][i] = 0.f;

    auto load_tiles = [&](int k0, int buf) {
        float* Ab = As + buf * A_BUF;
        float* Bb = Bs + buf * B_BUF;
#pragma unroll
        for (int it = 0; it < 4; ++it) {
            int idx = tid + it * 256;
            int r = idx >> 3, c4 = idx & 7;
            cp_async16(smem_u32(&Ab[r * A_STRIDE + c4 * 4]),
                       &A[(size_t)(bm + r) * K + k0 + c4 * 4]);
        }
#pragma unroll
        for (int it = 0; it < 4; ++it) {
            int idx = tid + it * 256;
            int r = idx >> 5, c4 = idx & 31;
            cp_async16(smem_u32(&Bb[r * B_STRIDE + c4 * 4]),
                       &Bm[(size_t)(k0 + r) * N + bn + c4 * 4]);
        }
        cp_commit();
    };

    load_tiles(0, 0);

    const int n_k = K / GBK;
    for (int kt = 0; kt < n_k; ++kt) {
        const int buf = kt & 1;
        if (kt + 1 < n_k) {
            load_tiles((kt + 1) * GBK, buf ^ 1);
            cp_wait1();
        } else {
            cp_wait0();
        }
        __syncthreads();

        const float* Ab = As + buf * A_BUF;
        const float* Bb = Bs + buf * B_BUF;

#pragma unroll
        for (int kk = 0; kk < GBK; kk += 8) {
            uint32_t a[2][4];
#pragma unroll
            for (int mt = 0; mt < 2; mt++) {
                const int r0 = wm + mt * 16 + g;
                a[mt][0] = __float_as_uint(Ab[(r0)     * A_STRIDE + kk + tg]);
                a[mt][1] = __float_as_uint(Ab[(r0 + 8) * A_STRIDE + kk + tg]);
                a[mt][2] = __float_as_uint(Ab[(r0)     * A_STRIDE + kk + tg + 4]);
                a[mt][3] = __float_as_uint(Ab[(r0 + 8) * A_STRIDE + kk + tg + 4]);
            }
#pragma unroll
            for (int nt = 0; nt < 8; nt++) {
                const int col = wn + nt * 8 + g;
                uint32_t b0 = __float_as_uint(Bb[(kk + tg)     * B_STRIDE + col]);
                uint32_t b1 = __float_as_uint(Bb[(kk + tg + 4) * B_STRIDE + col]);
#pragma unroll
                for (int mt = 0; mt < 2; mt++) {
                    mma_tf32_16x8x8(c[mt][nt],
                                    a[mt][0], a[mt][1], a[mt][2], a[mt][3],
                                    b0, b1);
                }
            }
        }
        __syncthreads();
    }

#pragma unroll
    for (int mt = 0; mt < 2; mt++) {
        const int r0 = bm + wm + mt * 16 + g;
#pragma unroll
        for (int nt = 0; nt < 8; nt++) {
            const int col = bn + wn + nt * 8 + tg * 2;
            float v0 = c[mt][nt][0], v1 = c[mt][nt][1];
            float v2 = c[mt][nt][2], v3 = c[mt][nt][3];
            if (round_out) {
                v0 = round_tf32(v0); v1 = round_tf32(v1);
                v2 = round_tf32(v2); v3 = round_tf32(v3);
            }
            *(float2*)&C[(size_t)r0 * N + col]       = make_float2(v0, v1);
            *(float2*)&C[(size_t)(r0 + 8) * N + col] = make_float2(v2, v3);
        }
    }
}

// ---------------------------------------------------------------------------
// Flash attention v3: TF32 tensor cores for QK^T and P@V.
// Block = (b, h, 128-query tile), 256 threads = 8 warps.
// Warp w owns query rows wm..wm+15 (wm = w*16). Per key tile (64 keys):
//   S (16x64) = Q(16x64) @ K^T via 8x8 m16n8k8 mma, softmax in registers
//   (row stats fully warp-local), P staged in warp-private smem rows,
//   O (16x64) += P(16x64) @ V via 8x8 mma.
// Smem strides: K 68 (banks 4g+tg), V 72 (8tg+g), Q/P 76 (12g+tg) -> all
// fragment loads conflict-free.
// ---------------------------------------------------------------------------
#define AT_Q 128
#define AT_K 64
#define KD 68
#define VD 72
#define PD 76
#define QP_FLOATS (AT_Q * PD)                  // 9728
#define K_FLOATS  (AT_K * KD)                  // 4352
#define V_FLOATS  (AT_K * VD)                  // 4608
#define ATTN_SMEM ((QP_FLOATS + 2 * K_FLOATS + 2 * V_FLOATS) * sizeof(float)) // 110592
#define NEG_INF_F (-1e30f)

__global__ __launch_bounds__(256, 2) void attn_kernel(
    const float* __restrict__ qkv, float* __restrict__ out)
{
    const int qt   = (int)gridDim.x - 1 - (int)blockIdx.x;  // heavy blocks first
    const int h    = blockIdx.y;
    const int b    = blockIdx.z;
    const int tid  = threadIdx.x;
    const int warp = tid >> 5;
    const int lane = tid & 31;
    const int g    = lane >> 2;
    const int tg   = lane & 3;
    const int wm   = warp * 16;

    extern __shared__ float sm[];
    float* QP = sm;                       // [128][76]  Q tile, then P staging
    float* Ks = sm + QP_FLOATS;           // [2][64][68]
    float* Vs = sm + QP_FLOATS + 2 * K_FLOATS;  // [2][64][72]

    const float scale = 0.125f;
    const size_t base = (size_t)b * S_ * 3 * D_ + (size_t)h * DH_;

    // group 0: Q tile + K/V tile 0
    {
#pragma unroll
        for (int it = 0; it < 8; ++it) {
            int idx = tid + it * 256;             // 0..2047
            int r = idx >> 4, c4 = idx & 15;
            cp_async16(smem_u32(&QP[r * PD + c4 * 4]),
                       &qkv[base + (size_t)(qt * AT_Q + r) * 3 * D_ + c4 * 4]);
        }
#pragma unroll
        for (int it = 0; it < 4; ++it) {
            int idx = tid + it * 256;             // 0..1023
            int r = idx >> 4, c4 = idx & 15;
            size_t gsrc = base + (size_t)r * 3 * D_ + c4 * 4;   // kt = 0
            cp_async16(smem_u32(&Ks[r * KD + c4 * 4]), &qkv[gsrc + D_]);
            cp_async16(smem_u32(&Vs[r * VD + c4 * 4]), &qkv[gsrc + 2 * D_]);
        }
        cp_commit();
    }

    uint32_t qa[8][4];           // Q fragments (k-steps 0..7)
    float o[8][4];
    float m0 = NEG_INF_F, m1 = NEG_INF_F, l0 = 0.f, l1 = 0.f;
#pragma unroll
    for (int nt = 0; nt < 8; nt++)
#pragma unroll
        for (int i = 0; i < 4; i++) o[nt][i] = 0.f;

    const int n_tiles = 2 * qt + 2;
    for (int kt = 0; kt < n_tiles; ++kt) {
        const int buf = kt & 1;
        if (kt > 0) __syncthreads();   // done with buf^1 from iter kt-1

        if (kt + 1 < n_tiles) {
            float* Kn = &Ks[(size_t)(buf ^ 1) * K_FLOATS];
            float* Vn = &Vs[(size_t)(buf ^ 1) * V_FLOATS];
#pragma unroll
            for (int it = 0; it < 4; ++it) {
                int idx = tid + it * 256;
                int r = idx >> 4, c4 = idx & 15;
                size_t gsrc = base + (size_t)((kt + 1) * AT_K + r) * 3 * D_ + c4 * 4;
                cp_async16(smem_u32(&Kn[r * KD + c4 * 4]), &qkv[gsrc + D_]);
                cp_async16(smem_u32(&Vn[r * VD + c4 * 4]), &qkv[gsrc + 2 * D_]);
            }
            cp_commit();
            cp_wait1();
        } else {
            cp_wait0();
        }
        __syncthreads();

        if (kt == 0) {
            // load Q fragments once (rows wm+g, wm+g+8 are warp-private)
#pragma unroll
            for (int k8 = 0; k8 < 8; k8++) {
                const int kk = k8 * 8;
                qa[k8][0] = __float_as_uint(QP[(wm + g)     * PD + kk + tg]);
                qa[k8][1] = __float_as_uint(QP[(wm + g + 8) * PD + kk + tg]);
                qa[k8][2] = __float_as_uint(QP[(wm + g)     * PD + kk + tg + 4]);
                qa[k8][3] = __float_as_uint(QP[(wm + g + 8) * PD + kk + tg + 4]);
            }
        }

        const float* Kb = &Ks[(size_t)buf * K_FLOATS];
        const float* Vb = &Vs[(size_t)buf * V_FLOATS];

        // ---- S = Q @ K^T  (16x64 per warp) ----
        float s[8][4];
#pragma unroll
        for (int nt = 0; nt < 8; nt++)
#pragma unroll
            for (int i = 0; i < 4; i++) s[nt][i] = 0.f;

#pragma unroll
        for (int k8 = 0; k8 < 8; k8++) {
            const int kk = k8 * 8;
#pragma unroll
            for (int nt = 0; nt < 8; nt++) {
                uint32_t b0 = __float_as_uint(Kb[(nt * 8 + g) * KD + kk + tg]);
                uint32_t b1 = __float_as_uint(Kb[(nt * 8 + g) * KD + kk + tg + 4]);
                mma_tf32_16x8x8(s[nt], qa[k8][0], qa[k8][1], qa[k8][2], qa[k8][3], b0, b1);
            }
        }

        // ---- mask + scale + online softmax (rows g, g+8 of warp strip) ----
        const int grow0 = qt * AT_Q + wm + g;
        const int grow1 = grow0 + 8;
        const bool interior = (kt * AT_K + AT_K - 1 <= qt * AT_Q + wm);

        float mx0 = NEG_INF_F, mx1 = NEG_INF_F;
#pragma unroll
        for (int nt = 0; nt < 8; nt++) {
            const int gc0 = kt * AT_K + nt * 8 + 2 * tg;
            s[nt][0] = (interior || gc0     <= grow0) ? s[nt][0] * scale : NEG_INF_F;
            s[nt][1] = (interior || gc0 + 1 <= grow0) ? s[nt][1] * scale : NEG_INF_F;
            s[nt][2] = (interior || gc0     <= grow1) ? s[nt][2] * scale : NEG_INF_F;
            s[nt][3] = (interior || gc0 + 1 <= grow1) ? s[nt][3] * scale : NEG_INF_F;
            mx0 = fmaxf(mx0, fmaxf(s[nt][0], s[nt][1]));
            mx1 = fmaxf(mx1, fmaxf(s[nt][2], s[nt][3]));
        }
        mx0 = fmaxf(mx0, __shfl_xor_sync(0xffffffffu, mx0, 1));
        mx0 = fmaxf(mx0, __shfl_xor_sync(0xffffffffu, mx0, 2));
        mx1 = fmaxf(mx1, __shfl_xor_sync(0xffffffffu, mx1, 1));
        mx1 = fmaxf(mx1, __shfl_xor_sync(0xffffffffu, mx1, 2));

        const float mn0 = fmaxf(m0, mx0);
        const float mn1 = fmaxf(m1, mx1);
        const float cr0 = __expf(m0 - mn0);
        const float cr1 = __expf(m1 - mn1);
        m0 = mn0; m1 = mn1;

        float sum0 = 0.f, sum1 = 0.f;
#pragma unroll
        for (int nt = 0; nt < 8; nt++) {
            s[nt][0] = __expf(s[nt][0] - mn0);
            s[nt][1] = __expf(s[nt][1] - mn0);
            s[nt][2] = __expf(s[nt][2] - mn1);
            s[nt][3] = __expf(s[nt][3] - mn1);
            sum0 += s[nt][0] + s[nt][1];
            sum1 += s[nt][2] + s[nt][3];
        }
        sum0 += __shfl_xor_sync(0xffffffffu, sum0, 1);
        sum0 += __shfl_xor_sync(0xffffffffu, sum0, 2);
        sum1 += __shfl_xor_sync(0xffffffffu, sum1, 1);
        sum1 += __shfl_xor_sync(0xffffffffu, sum1, 2);
        l0 = l0 * cr0 + sum0;
        l1 = l1 * cr1 + sum1;

#pragma unroll
        for (int nt = 0; nt < 8; nt++) {
            o[nt][0] *= cr0; o[nt][1] *= cr0;
            o[nt][2] *= cr1; o[nt][3] *= cr1;
        }

        // ---- stage P (tf32) in warp-private rows of QP ----
#pragma unroll
        for (int nt = 0; nt < 8; nt++) {
            *(float2*)&QP[(wm + g)     * PD + nt * 8 + 2 * tg] =
                make_float2(round_tf32(s[nt][0]), round_tf32(s[nt][1]));
            *(float2*)&QP[(wm + g + 8) * PD + nt * 8 + 2 * tg] =
                make_float2(round_tf32(s[nt][2]), round_tf32(s[nt][3]));
        }
        __syncwarp();

        // ---- O += P @ V  (16x64 per warp) ----
#pragma unroll
        for (int k8 = 0; k8 < 8; k8++) {
            const int kk = k8 * 8;
            uint32_t a0 = __float_as_uint(QP[(wm + g)     * PD + kk + tg]);
            uint32_t a1 = __float_as_uint(QP[(wm + g + 8) * PD + kk + tg]);
            uint32_t a2 = __float_as_uint(QP[(wm + g)     * PD + kk + tg + 4]);
            uint32_t a3 = __float_as_uint(QP[(wm + g + 8) * PD + kk + tg + 4]);
#pragma unroll
            for (int nt = 0; nt < 8; nt++) {
                uint32_t b0 = __float_as_uint(Vb[(kk + tg)     * VD + nt * 8 + g]);
                uint32_t b1 = __float_as_uint(Vb[(kk + tg + 4) * VD + nt * 8 + g]);
                mma_tf32_16x8x8(o[nt], a0, a1, a2, a3, b0, b1);
            }
        }
    }

    // ---- epilogue: normalize, tf32-round (feeds out-proj), store ----
    const float inv0 = 1.f / l0;
    const float inv1 = 1.f / l1;
    const size_t row0 = (size_t)(b * S_ + qt * AT_Q + wm + g);
#pragma unroll
    for (int nt = 0; nt < 8; nt++) {
        const int col = h * DH_ + nt * 8 + 2 * tg;
        *(float2*)&out[row0 * D_ + col] =
            make_float2(round_tf32(o[nt][0] * inv0), round_tf32(o[nt][1] * inv0));
        *(float2*)&out[(row0 + 8) * D_ + col] =
            make_float2(round_tf32(o[nt][2] * inv1), round_tf32(o[nt][3] * inv1));
    }
}

// ---------------------------------------------------------------------------
// Launch
// ---------------------------------------------------------------------------
extern "C" void kernel_launch(void* const* d_in, const int* in_sizes, int n_in,
                              void* d_out, int out_size)
{
    const float* x     = (const float*)d_in[0];   // [4096,1024]
    const float* w_qkv = (const float*)d_in[1];   // [1024,3072]
    const float* w_out = (const float*)d_in[2];   // [1024,1024]
    float* out = (float*)d_out;                   // [4096,1024]

    float *qkv, *attn, *xr, *wqkvr, *woutr;
    cudaGetSymbolAddress((void**)&qkv,   g_qkv);
    cudaGetSymbolAddress((void**)&attn,  g_attn);
    cudaGetSymbolAddress((void**)&xr,    g_x);
    cudaGetSymbolAddress((void**)&wqkvr, g_wqkv);
    cudaGetSymbolAddress((void**)&woutr, g_wout);

    // 0) Pre-round GEMM operands to exact tf32 (round-to-nearest)
    round_tf32_kernel<<<592, 256>>>(x,     xr,    M_TOK * D_ / 4);
    round_tf32_kernel<<<592, 256>>>(w_qkv, wqkvr, D_ * 3 * D_ / 4);
    round_tf32_kernel<<<592, 256>>>(w_out, woutr, D_ * D_ / 4);

    // 1) QKV projection (tf32 TC), epilogue rounds to tf32 for attention
    {
        cudaFuncSetAttribute(mma_gemm_kernel,
                             cudaFuncAttributeMaxDynamicSharedMemorySize,
                             (int)GEMM_SMEM);
        dim3 grid(3 * D_ / GBN, M_TOK / GBM);
        mma_gemm_kernel<<<grid, 256, GEMM_SMEM>>>(xr, wqkvr, qkv, M_TOK, 3 * D_, D_, 1);
    }

    // 2) Flash attention (tf32 TC)
    {
        cudaFuncSetAttribute(attn_kernel,
                             cudaFuncAttributeMaxDynamicSharedMemorySize,
                             (int)ATTN_SMEM);
        dim3 grid(S_ / AT_Q, H_, B_);
        attn_kernel<<<grid, 256, ATTN_SMEM>>>(qkv, attn);
    }

    // 3) Output projection (tf32 TC), plain fp32 epilogue
    {
        dim3 grid(D_ / GBN, M_TOK / GBM);
        mma_gemm_kernel<<<grid, 256, GEMM_SMEM>>>(attn, woutr, out, M_TOK, D_, D_, 0);
    }
}